// round 2
// baseline (speedup 1.0000x reference)
#include <cuda_runtime.h>
#include <cuda_bf16.h>

#define D_DIM     128
#define N_RBF     50
#define K_PAD     52            // pad to multiple of 4 for float4 LDS
#define E_TILE    32            // edges per tile in edge kernel
#define MAX_NODES 50000
#define CUTOFF_F  5.0f
#define PI_OVER_CUTOFF 0.62831853071795864769f

// scatter-sum accumulator (device global scratch; no cudaMalloc allowed)
__device__ float g_acc[(size_t)MAX_NODES * D_DIM];

// ---------------------------------------------------------------------------
// Kernel 1: zero the accumulator
// ---------------------------------------------------------------------------
__global__ void zero_kernel(int n4) {
    int i = blockIdx.x * blockDim.x + threadIdx.x;
    if (i < n4) {
        ((float4*)g_acc)[i] = make_float4(0.f, 0.f, 0.f, 0.f);
    }
}

// ---------------------------------------------------------------------------
// Kernel 2: edge kernel.
//   Thread d (0..127) owns output dim d; W_e[d,0:50] lives in 52 registers
//   (2 zero-padded). rbf tile staged in smem, broadcast LDS.128 reads.
//   msg staged in smem, then scattered with vectorized float4 atomicAdd
//   (one RED.E.128 warp-instruction per edge).
// ---------------------------------------------------------------------------
__global__ void __launch_bounds__(128) edge_kernel(
    const float* __restrict__ rbf,       // [E, 50]
    const float* __restrict__ dist,      // [E]
    const int*   __restrict__ src,       // [E]
    const int*   __restrict__ dst,       // [E]
    const int*   __restrict__ node_type, // [N]
    const float* __restrict__ emb,       // [100, 128]
    const float* __restrict__ W_e,       // [128, 50]
    const float* __restrict__ b_e,       // [128]
    int n_edges)
{
    __shared__ float rbf_sh[E_TILE][K_PAD];
    __shared__ float msg_sh[E_TILE][D_DIM];
    __shared__ float w_sh[E_TILE];   // cutoff weight
    __shared__ int   dst_sh[E_TILE];
    __shared__ int   typ_sh[E_TILE];

    const int tid = threadIdx.x;      // == output dim d
    const int d   = tid;

    // load my W_e row into registers (zero-padded)
    float wreg[K_PAD];
#pragma unroll
    for (int k = 0; k < N_RBF; k++) wreg[k] = W_e[d * N_RBF + k];
#pragma unroll
    for (int k = N_RBF; k < K_PAD; k++) wreg[k] = 0.f;
    const float be = b_e[d];

    const int num_tiles = (n_edges + E_TILE - 1) / E_TILE;
    for (int tile = blockIdx.x; tile < num_tiles; tile += gridDim.x) {
        const int e0 = tile * E_TILE;
        const int nE = min(E_TILE, n_edges - e0);

        // cooperative load of rbf tile (coalesced; contiguous E_TILE*50 floats)
        for (int i = tid; i < nE * N_RBF; i += blockDim.x) {
            int e = i / N_RBF;
            int k = i - e * N_RBF;
            rbf_sh[e][k] = rbf[(size_t)e0 * N_RBF + i];
        }
        if (tid < E_TILE) {
            rbf_sh[tid][N_RBF]     = 0.f;
            rbf_sh[tid][N_RBF + 1] = 0.f;
        }
        if (tid < nE) {
            float dd = dist[e0 + tid];
            float w  = 0.5f * (cosf(dd * PI_OVER_CUTOFF) + 1.0f);
            w_sh[tid]   = (dd < CUTOFF_F) ? w : 0.f;
            int s       = src[e0 + tid];
            typ_sh[tid] = node_type[s];
            dst_sh[tid] = dst[e0 + tid];
        }
        __syncthreads();

        // per-edge dot product: 13 float4 broadcast LDS + 52 FFMA, 4 accum chains
        for (int e = 0; e < nE; e++) {
            float a0 = 0.f, a1 = 0.f, a2 = 0.f, a3 = 0.f;
#pragma unroll
            for (int k = 0; k < K_PAD; k += 4) {
                float4 r = *(const float4*)&rbf_sh[e][k];
                a0 = fmaf(r.x, wreg[k],     a0);
                a1 = fmaf(r.y, wreg[k + 1], a1);
                a2 = fmaf(r.z, wreg[k + 2], a2);
                a3 = fmaf(r.w, wreg[k + 3], a3);
            }
            float xe = (a0 + a1) + (a2 + a3) + be;
            float m  = __ldg(&emb[(size_t)typ_sh[e] * D_DIM + d]) * xe * w_sh[e];
            msg_sh[e][d] = m;
        }
        __syncthreads();

        // vectorized scatter: warp w handles edges w, w+4, ...
        // one float4 atomicAdd per lane -> one RED.E.128 warp-instr per edge
        const int warp = tid >> 5, lane = tid & 31;
        for (int e = warp; e < nE; e += 4) {
            float4 v = *(const float4*)&msg_sh[e][lane * 4];
            atomicAdd((float4*)&g_acc[(size_t)dst_sh[e] * D_DIM + lane * 4], v);
        }
        __syncthreads();
    }
}

// ---------------------------------------------------------------------------
// Kernel 3: out = x_nodes @ Wc[:, :128].T + g_acc @ Wc[:, 128:].T + b_c
//   256 threads: tid = h*128 + d.  half h covers 128 of the 256 j's.
//   W_c transposed into smem, per-thread row with stride 132 floats
//   (132 = 4*33, odd multiplier -> conflict-free LDS.128 phases).
//   8-node register blocking: per 4-j quad, 1 W LDS.128 + 8 x LDS.128 + 32 FFMA.
// ---------------------------------------------------------------------------
#define NT 8
#define W_STRIDE 132

__global__ void __launch_bounds__(256) out_kernel(
    const float* __restrict__ x_nodes,  // [N, 128]
    const float* __restrict__ W_c,      // [128, 256]
    const float* __restrict__ b_c,      // [128]
    float* __restrict__ out,            // [N, 128]
    int n_nodes)
{
    extern __shared__ float sh[];
    float* w_sh  = sh;                           // 256 * 132
    float* x_sh  = w_sh + 256 * W_STRIDE;        // NT * 256
    float* ps_sh = x_sh + NT * 256;              // NT * 128

    const int tid = threadIdx.x;
    const int h   = tid >> 7;        // which j-half (0: x_nodes, 1: g_acc)
    const int d   = tid & 127;       // output dim

    // load + transpose W_c into smem: row (h*128+d) holds W_c[d][h*128 .. h*128+127]
    for (int i = tid; i < 128 * 256; i += 256) {
        int dd = i >> 8;
        int j  = i & 255;
        w_sh[((j >> 7) * 128 + dd) * W_STRIDE + (j & 127)] = W_c[i];
    }
    const float bcv = b_c[d];
    __syncthreads();

    const float* wrow = &w_sh[tid * W_STRIDE];
    const int num_tiles = (n_nodes + NT - 1) / NT;

    for (int t = blockIdx.x; t < num_tiles; t += gridDim.x) {
        const int n0 = t * NT;
        const int nN = min(NT, n_nodes - n0);

        // stage x tile: rows = [x_nodes row | g_acc row], 256 floats each
        for (int i = tid; i < nN * 64; i += 256) {
            int n = i >> 6, q = i & 63;
            float4 v;
            if (q < 32) v = *(const float4*)&x_nodes[(size_t)(n0 + n) * 128 + q * 4];
            else        v = *(const float4*)&g_acc [(size_t)(n0 + n) * 128 + (q - 32) * 4];
            *(float4*)&x_sh[n * 256 + q * 4] = v;
        }
        __syncthreads();

        float acc[NT];
#pragma unroll
        for (int n = 0; n < NT; n++) acc[n] = 0.f;

        const float* xbase = x_sh + h * 128;
#pragma unroll
        for (int jq = 0; jq < 32; jq++) {
            float4 w = *(const float4*)&wrow[jq * 4];
#pragma unroll
            for (int n = 0; n < NT; n++) {
                float4 x = *(const float4*)&xbase[n * 256 + jq * 4];
                acc[n] = fmaf(x.w, w.w,
                         fmaf(x.z, w.z,
                         fmaf(x.y, w.y,
                         fmaf(x.x, w.x, acc[n]))));
            }
        }

        // combine halves
        if (h == 1) {
#pragma unroll
            for (int n = 0; n < NT; n++) ps_sh[n * 128 + d] = acc[n];
        }
        __syncthreads();
        if (h == 0) {
            for (int n = 0; n < nN; n++) {
                out[(size_t)(n0 + n) * 128 + d] = acc[n] + ps_sh[n * 128 + d] + bcv;
            }
        }
        __syncthreads();
    }
}

// ---------------------------------------------------------------------------
// Launch
// ---------------------------------------------------------------------------
extern "C" void kernel_launch(void* const* d_in, const int* in_sizes, int n_in,
                              void* d_out, int out_size)
{
    const int*   node_type = (const int*)  d_in[0];
    const float* x_nodes   = (const float*)d_in[1];
    const int*   src       = (const int*)  d_in[2];
    const int*   dst       = (const int*)  d_in[3];
    const float* rbf       = (const float*)d_in[4];
    const float* dist      = (const float*)d_in[5];
    const float* emb       = (const float*)d_in[6];
    const float* W_e       = (const float*)d_in[7];
    const float* b_e       = (const float*)d_in[8];
    const float* W_c       = (const float*)d_in[9];
    const float* b_c       = (const float*)d_in[10];
    float* out = (float*)d_out;

    const int n_nodes = in_sizes[0];
    const int n_edges = in_sizes[2];

    // 1) zero accumulator
    int n4 = n_nodes * D_DIM / 4;
    zero_kernel<<<(n4 + 255) / 256, 256>>>(n4);

    // 2) edge projection + gather-multiply-scatter
    edge_kernel<<<760, 128>>>(rbf, dist, src, dst, node_type, emb, W_e, b_e, n_edges);

    // 3) final combine GEMM
    size_t shmem = (256 * W_STRIDE + NT * 256 + NT * 128) * sizeof(float);
    cudaFuncSetAttribute(out_kernel, cudaFuncAttributeMaxDynamicSharedMemorySize, (int)shmem);
    out_kernel<<<152, 256, shmem>>>(x_nodes, W_c, b_c, out, n_nodes);
}